// round 8
// baseline (speedup 1.0000x reference)
#include <cuda_runtime.h>
#include <cstdint>

#define N_ROWS 65536
#define DIM    512
#define KC     256
#define BM     64        // rows per CTA
#define DT     16        // d per chunk
#define NCHNK  (DIM/DT)  // 32
#define NTHR   256
#define TAU    0.01f

typedef unsigned long long ull;

// centroids pre-transposed pair-major: g_c2[kp][d] = (C[2kp][d], C[2kp+1][d])
__device__ float2 g_c2[KC/2][DIM];
__device__ float  g_cnorm[KC];
__device__ int    g_idx[N_ROWS];
__device__ int    g_flag_cnt;
__device__ int    g_flag_rows[N_ROWS];

__device__ __forceinline__ uint32_t smem_u32(const void* p) {
    uint32_t a;
    asm("{ .reg .u64 t; cvta.to.shared.u64 t, %1; cvt.u32.u64 %0, t; }" : "=r"(a) : "l"(p));
    return a;
}
__device__ __forceinline__ void cp16(uint32_t s, const void* g) {
    asm volatile("cp.async.cg.shared.global [%0], [%1], 16;" :: "r"(s), "l"(g) : "memory");
}
__device__ __forceinline__ ull pack2(float x, float y) {
    ull r; asm("mov.b64 %0, {%1, %2};" : "=l"(r) : "f"(x), "f"(y)); return r;
}
__device__ __forceinline__ void fma2(ull& d, ull a, ull b) {
    asm("fma.rn.f32x2 %0, %1, %2, %0;" : "+l"(d) : "l"(a), "l"(b));
}
__device__ __forceinline__ float2 unpack2(ull v) {
    float2 r; asm("mov.b64 {%0, %1}, %2;" : "=f"(r.x), "=f"(r.y) : "l"(v)); return r;
}
__device__ __forceinline__ bool ltp(float a, int ia, float b, int ib) {
    return a < b || (a == b && ia < ib);
}

// ---------------------------------------------------------------------------
__global__ void prep_kernel(const float* __restrict__ C) {
    __shared__ double red[4];
    const int k = blockIdx.x, t = threadIdx.x;   // 128 thr
    if (k == 0 && t == 0) g_flag_cnt = 0;        // deterministic across replays
    double s = 0.0;
    for (int d = t; d < DIM; d += 128) {
        float v = C[(size_t)k * DIM + d];
        s += (double)v * (double)v;
        ((float*)(&g_c2[k >> 1][d]))[k & 1] = v;
    }
    #pragma unroll
    for (int o = 16; o; o >>= 1) s += __shfl_xor_sync(0xffffffffu, s, o);
    if ((t & 31) == 0) red[t >> 5] = s;
    __syncthreads();
    if (t == 0) g_cnorm[k] = (float)(red[0] + red[1] + red[2] + red[3]);
}

// ---------------------------------------------------------------------------
// Score kernel. CTA: 64 rows x 256 cents. Warp ry owns rows [8ry, 8ry+8);
// lane cx owns centroid pairs {cx, cx+32, cx+64, cx+96}.
// Smem tiles are 128B-row, granule(16B)-XOR-swizzled for conflict-free LDS.128.
// ---------------------------------------------------------------------------
__global__ __launch_bounds__(NTHR, 2) void score_kernel(const float* __restrict__ E)
{
    __shared__ __align__(16) ull e2s[BM * DT];          // 8KB  [row][8 granules]
    __shared__ __align__(16) ull c2s[2][(KC/2) * DT];   // 2x16KB [kp][8 granules]
    __shared__ float cnS[KC];

    const uint32_t e2b = smem_u32(e2s);
    const uint32_t c2b0 = smem_u32(&c2s[0][0]);
    const int tid  = threadIdx.x;
    const int cx   = tid & 31;
    const int ry   = tid >> 5;
    const int row0 = blockIdx.x * BM;

    for (int i = tid; i < KC; i += NTHR) cnS[i] = g_cnorm[i];

    // E staging: thread -> (row r, quad q)
    const int er = tid >> 2;
    const int eq = tid & 3;

    // ---- prologue: cp.async C chunk 0, LDG E chunk 0 ----
    {
        #pragma unroll
        for (int j = 0; j < 4; j++) {
            int u = tid + NTHR * j;          // 1024 16B units: kp = u>>3, g = u&7
            int kp = u >> 3, g = u & 7;
            cp16(c2b0 + kp * 128 + ((g ^ (kp & 7)) << 4),
                 (const char*)g_c2 + (size_t)kp * DIM * 8 + g * 16);
        }
        asm volatile("cp.async.commit_group;" ::: "memory");
    }
    float4 estage = *(const float4*)(E + (size_t)(row0 + er) * DIM + eq * 4);

    ull acc[8][4];
    #pragma unroll
    for (int j = 0; j < 8; j++)
        #pragma unroll
        for (int p = 0; p < 4; p++) acc[j][p] = 0ull;

    for (int ch = 0; ch < NCHNK; ch++) {
        // store staged E (duplicated pairs, swizzled)
        {
            float f[4] = {estage.x, estage.y, estage.z, estage.w};
            #pragma unroll
            for (int i = 0; i < 4; i++) {
                int d = eq * 4 + i;
                int gs = (d >> 1) ^ (er & 7);
                *(ull*)((char*)e2s + er * 128 + (gs << 4) + ((d & 1) << 3)) = pack2(f[i], f[i]);
            }
        }
        // prefetch next chunk
        if (ch + 1 < NCHNK) {
            uint32_t cdst = c2b0 + ((ch + 1) & 1) * (16384);
            const char* csrc = (const char*)g_c2 + (ch + 1) * (DT * 8);
            #pragma unroll
            for (int j = 0; j < 4; j++) {
                int u = tid + NTHR * j;
                int kp = u >> 3, g = u & 7;
                cp16(cdst + kp * 128 + ((g ^ (kp & 7)) << 4),
                     csrc + (size_t)kp * DIM * 8 + g * 16);
            }
            asm volatile("cp.async.commit_group;" ::: "memory");
            estage = *(const float4*)(E + (size_t)(row0 + er) * DIM + (ch + 1) * DT + eq * 4);
            asm volatile("cp.async.wait_group 1;" ::: "memory");
        } else {
            asm volatile("cp.async.wait_group 0;" ::: "memory");
        }
        __syncthreads();

        // ---- compute 16 d (8 iterations of 2 d via LDS.128) ----
        const char* cb = (const char*)&c2s[ch & 1][0];
        #pragma unroll
        for (int it = 0; it < 8; it++) {
            ulonglong2 cv[4];
            #pragma unroll
            for (int p = 0; p < 4; p++) {
                int kp = cx + 32 * p;
                cv[p] = *(const ulonglong2*)(cb + kp * 128 + ((it ^ (kp & 7)) << 4));
            }
            #pragma unroll
            for (int j = 0; j < 8; j++) {
                ulonglong2 ev = *(const ulonglong2*)((const char*)e2s + (ry * 8 + j) * 128
                                                     + ((it ^ j) << 4));
                #pragma unroll
                for (int p = 0; p < 4; p++) {
                    fma2(acc[j][p], ev.x, cv[p].x);
                    fma2(acc[j][p], ev.y, cv[p].y);
                }
            }
        }
        __syncthreads();
    }

    // ---- per-row top-3: per-lane insertion over 8 scores, butterfly merge ----
    #pragma unroll
    for (int j = 0; j < 8; j++) {
        float v1 = 3.4e38f, v2 = 3.4e38f, v3 = 3.4e38f;
        int   i1 = 0x7fffffff, i2 = 0x7fffffff, i3 = 0x7fffffff;
        #pragma unroll
        for (int p = 0; p < 4; p++) {
            float2 dd = unpack2(acc[j][p]);
            int kp = cx + 32 * p;
            float s0 = cnS[2 * kp]     - 2.0f * dd.x;
            float s1 = cnS[2 * kp + 1] - 2.0f * dd.y;
            int a0 = 2 * kp, a1 = 2 * kp + 1;
            if (ltp(s0, a0, v1, i1))      { v3=v2;i3=i2; v2=v1;i2=i1; v1=s0;i1=a0; }
            else if (ltp(s0, a0, v2, i2)) { v3=v2;i3=i2; v2=s0;i2=a0; }
            else if (ltp(s0, a0, v3, i3)) { v3=s0;i3=a0; }
            if (ltp(s1, a1, v1, i1))      { v3=v2;i3=i2; v2=v1;i2=i1; v1=s1;i1=a1; }
            else if (ltp(s1, a1, v2, i2)) { v3=v2;i3=i2; v2=s1;i2=a1; }
            else if (ltp(s1, a1, v3, i3)) { v3=s1;i3=a1; }
        }
        #pragma unroll
        for (int off = 16; off; off >>= 1) {
            float ov[3]; int oi[3];
            ov[0] = __shfl_xor_sync(0xffffffffu, v1, off);
            oi[0] = __shfl_xor_sync(0xffffffffu, i1, off);
            ov[1] = __shfl_xor_sync(0xffffffffu, v2, off);
            oi[1] = __shfl_xor_sync(0xffffffffu, i2, off);
            ov[2] = __shfl_xor_sync(0xffffffffu, v3, off);
            oi[2] = __shfl_xor_sync(0xffffffffu, i3, off);
            #pragma unroll
            for (int q = 0; q < 3; q++) {
                if (ltp(ov[q], oi[q], v1, i1))      { v3=v2;i3=i2; v2=v1;i2=i1; v1=ov[q];i1=oi[q]; }
                else if (ltp(ov[q], oi[q], v2, i2)) { v3=v2;i3=i2; v2=ov[q];i2=oi[q]; }
                else if (ltp(ov[q], oi[q], v3, i3)) { v3=ov[q];i3=oi[q]; }
            }
        }
        if (cx == 0) {
            int row = row0 + ry * 8 + j;
            g_idx[row] = i2;
            if ((v2 - v1 <= TAU) || (v3 - v2 <= TAU)) {
                int p = atomicAdd(&g_flag_cnt, 1);
                g_flag_rows[p] = row;
            }
        }
    }
}

// ---------------------------------------------------------------------------
// Cleanup: exact full 256-cent rescan of flagged rows -> fixes g_idx.
// ---------------------------------------------------------------------------
__global__ void cleanup_kernel(const float* __restrict__ E, const float* __restrict__ C)
{
    __shared__ float es[DIM];
    __shared__ float sc[KC];
    const int t = threadIdx.x;    // 256
    const int nflag = g_flag_cnt;
    for (int i = blockIdx.x; i < nflag; i += gridDim.x) {
        int row = g_flag_rows[i];
        __syncthreads();
        for (int d = t; d < DIM; d += 256) es[d] = E[(size_t)row * DIM + d];
        __syncthreads();
        const float* cr = C + (size_t)t * DIM;
        float acc = 0.0f;
        for (int c0 = 0; c0 < DIM; c0 += 16) {
            float p = 0.0f;
            #pragma unroll
            for (int dd = 0; dd < 16; dd++) p = fmaf(es[c0 + dd], cr[c0 + dd], p);
            acc += p;
        }
        sc[t] = g_cnorm[t] - 2.0f * acc;
        __syncthreads();
        if (t == 0) {
            float v1 = 3.4e38f, v2 = 3.4e38f; int j1 = -1, j2 = -1;
            for (int k = 0; k < KC; k++) {
                float s = sc[k];
                if (ltp(s, k, v1, j1))      { v2 = v1; j2 = j1; v1 = s; j1 = k; }
                else if (ltp(s, k, v2, j2)) { v2 = s; j2 = k; }
            }
            g_idx[row] = j2;
        }
        __syncthreads();
    }
}

// ---------------------------------------------------------------------------
// Gather: out[row] = C[g_idx[row]]  (measured 22us, 42% HBM)
// ---------------------------------------------------------------------------
__global__ __launch_bounds__(256) void gather_kernel(const float* __restrict__ C,
                                                     float* __restrict__ out)
{
    __shared__ int idxS[32];
    const int t = threadIdx.x;
    const int row0 = blockIdx.x * 32;
    if (t < 32) idxS[t] = g_idx[row0 + t];
    __syncthreads();
    #pragma unroll
    for (int j = 0; j < 16; j++) {
        int u = t + 256 * j;                 // 4096 float4 units
        int r = u >> 7, q = u & 127;
        *(float4*)(out + (size_t)(row0 + r) * DIM + q * 4) =
            *(const float4*)(C + (size_t)idxS[r] * DIM + q * 4);
    }
}

extern "C" void kernel_launch(void* const* d_in, const int* in_sizes, int n_in,
                              void* d_out, int out_size) {
    const float* E = (const float*)d_in[0];
    const float* C = (const float*)d_in[1];
    float* out = (float*)d_out;
    (void)in_sizes; (void)n_in; (void)out_size;

    prep_kernel<<<KC, 128>>>(C);
    score_kernel<<<N_ROWS / BM, NTHR>>>(E);
    cleanup_kernel<<<256, 256>>>(E, C);
    gather_kernel<<<N_ROWS / 32, 256>>>(C, out);
}

// round 9
// speedup vs baseline: 1.1810x; 1.1810x over previous
#include <cuda_runtime.h>
#include <cuda_bf16.h>
#include <cstdint>

#define N_ROWS 65536
#define DIM    512
#define KC     256
#define BM     32        // rows per CTA
#define CCH    32        // centroids per chunk
#define NCHK   8
#define NTHR   128
#define NCAND  8
#define TAU    1.0f

// smem byte offsets (dynamic)
#define OFF_A    0                 // 32 x 512 bf16 = 32768
#define OFF_B0   32768             // 32 x 512 bf16 = 32768
#define OFF_B1   65536
#define OFF_SC   98304             // 32 x 33 f32 = 4224
#define OFF_CN   102528            // 256 f32
#define OFF_CAND 103552            // 32 x 8 int
#define SMEM_TOTAL 104576          // ~102KB -> 2 CTAs/SM

__device__ __nv_bfloat16 g_Bbf[KC][DIM];
__device__ float g_cnorm[KC];
__device__ int   g_idx[N_ROWS];
__device__ int   g_flag_cnt;
__device__ int   g_flag_rows[N_ROWS];

__device__ __forceinline__ uint32_t smem_u32(const void* p) {
    uint32_t a;
    asm("{ .reg .u64 t; cvta.to.shared.u64 t, %1; cvt.u32.u64 %0, t; }" : "=r"(a) : "l"(p));
    return a;
}
__device__ __forceinline__ void cp16(uint32_t s, const void* g) {
    asm volatile("cp.async.cg.shared.global [%0], [%1], 16;" :: "r"(s), "l"(g) : "memory");
}
__device__ __forceinline__ void ldsm4(uint32_t& r0, uint32_t& r1, uint32_t& r2, uint32_t& r3, uint32_t a) {
    asm volatile("ldmatrix.sync.aligned.m8n8.x4.shared.b16 {%0,%1,%2,%3}, [%4];"
                 : "=r"(r0), "=r"(r1), "=r"(r2), "=r"(r3) : "r"(a));
}
__device__ __forceinline__ void mma16816(float* d, const uint32_t* a, const uint32_t* b) {
    asm volatile("mma.sync.aligned.m16n8k16.row.col.f32.bf16.bf16.f32 "
                 "{%0,%1,%2,%3}, {%4,%5,%6,%7}, {%8,%9}, {%0,%1,%2,%3};"
                 : "+f"(d[0]), "+f"(d[1]), "+f"(d[2]), "+f"(d[3])
                 : "r"(a[0]), "r"(a[1]), "r"(a[2]), "r"(a[3]), "r"(b[0]), "r"(b[1]));
}
__device__ __forceinline__ uint32_t b2u(__nv_bfloat162 v) {
    return ((uint32_t)__bfloat16_as_ushort(v.y) << 16) | __bfloat16_as_ushort(v.x);
}
__device__ __forceinline__ bool ltp(float a, int ia, float b, int ib) {
    return a < b || (a == b && ia < ib);
}

// ---------------------------------------------------------------------------
__global__ void prep_kernel(const float* __restrict__ C) {
    __shared__ double red[4];
    const int k = blockIdx.x, t = threadIdx.x;   // 128 thr
    if (k == 0 && t == 0) g_flag_cnt = 0;
    double s = 0.0;
    for (int d = t; d < DIM; d += 128) {
        float v = C[(size_t)k * DIM + d];
        s += (double)v * (double)v;
        g_Bbf[k][d] = __float2bfloat16_rn(v);
    }
    #pragma unroll
    for (int o = 16; o; o >>= 1) s += __shfl_xor_sync(0xffffffffu, s, o);
    if ((t & 31) == 0) red[t >> 5] = s;
    __syncthreads();
    if (t == 0) g_cnorm[k] = (float)(red[0] + red[1] + red[2] + red[3]);
}

// ---------------------------------------------------------------------------
// Score kernel: 32 rows x 256 cents per CTA, HMMA coarse + exact rescore.
// ---------------------------------------------------------------------------
__global__ __launch_bounds__(NTHR, 2) void score_kernel(
    const float* __restrict__ E, const float* __restrict__ C)
{
    extern __shared__ __align__(1024) char smem[];
    const uint32_t sb = smem_u32(smem);
    const int tid  = threadIdx.x;
    const int wid  = tid >> 5;      // 0..3
    const int lane = tid & 31;
    const int row0 = blockIdx.x * BM;

    float* scoreS = (float*)(smem + OFF_SC);
    float* cnS    = (float*)(smem + OFF_CN);
    int*   candS  = (int*)(smem + OFF_CAND);

    for (int i = tid; i < KC; i += NTHR) cnS[i] = g_cnorm[i];

    // ---- prefetch B chunk 0 (32 cents x 512d bf16 = 32KB) ----
    {
        const char* bsrc = (const char*)g_Bbf;
        #pragma unroll
        for (int j = 0; j < 16; j++) {
            int u = tid + NTHR * j;              // 2048 16B units: n = u>>6, c = u&63
            int n = u >> 6, c = u & 63;
            cp16(sb + OFF_B0 + n * 1024 + ((c ^ (n & 7)) << 4), bsrc + n * 1024 + c * 16);
        }
        asm volatile("cp.async.commit_group;" ::: "memory");
    }

    // ---- fill A: 32 rows of E, f32 -> bf16, swizzled ----
    #pragma unroll
    for (int j = 0; j < 32; j++) {
        int u = tid + NTHR * j;                  // 4096 float4 units
        int r = u >> 7, q = u & 127;
        float4 f = *(const float4*)(E + (size_t)(row0 + r) * DIM + q * 4);
        uint2 v = make_uint2(b2u(__floats2bfloat162_rn(f.x, f.y)),
                             b2u(__floats2bfloat162_rn(f.z, f.w)));
        uint32_t off = r * 1024 + (((q >> 1) ^ (r & 7)) << 4) + ((q & 1) << 3);
        *(uint2*)(smem + OFF_A + off) = v;
    }

    const int row0w = (wid & 1) * 16;
    const int c0w   = (wid >> 1) * 16;
    const int a_row  = row0w + (lane & 7) + ((lane >> 3) & 1) * 8;
    const int a_k8s  = (lane >> 4);
    const int b_nloc = c0w + ((lane >> 4) & 1) * 8 + (lane & 7);
    const int b_k8s  = (lane >> 3) & 1;

    const int selrow  = tid >> 2;
    const int selpart = tid & 3;
    float tv[NCAND]; int ti[NCAND];
    #pragma unroll
    for (int q = 0; q < NCAND; q++) { tv[q] = 3.4e38f; ti[q] = 0x7fffffff; }

    for (int nc = 0; nc < NCHK; nc++) {
        if (nc + 1 < NCHK) {
            const char* bsrc = (const char*)g_Bbf + (size_t)(nc + 1) * CCH * 1024;
            uint32_t bdst = sb + (((nc + 1) & 1) ? OFF_B1 : OFF_B0);
            #pragma unroll
            for (int j = 0; j < 16; j++) {
                int u = tid + NTHR * j;
                int n = u >> 6, c = u & 63;
                cp16(bdst + n * 1024 + ((c ^ (n & 7)) << 4), bsrc + n * 1024 + c * 16);
            }
            asm volatile("cp.async.commit_group;" ::: "memory");
            asm volatile("cp.async.wait_group 1;" ::: "memory");
        } else {
            asm volatile("cp.async.wait_group 0;" ::: "memory");
        }
        __syncthreads();

        const uint32_t aB = sb + OFF_A;
        const uint32_t bB = sb + ((nc & 1) ? OFF_B1 : OFF_B0);

        float d[2][4];
        #pragma unroll
        for (int nt = 0; nt < 2; nt++)
            #pragma unroll
            for (int e = 0; e < 4; e++) d[nt][e] = 0.0f;

        #pragma unroll 4
        for (int k16 = 0; k16 < 32; k16++) {
            uint32_t a[4];
            {
                int k8 = k16 * 2 + a_k8s;
                ldsm4(a[0], a[1], a[2], a[3],
                      aB + a_row * 1024 + ((k8 ^ (a_row & 7)) << 4));
            }
            uint32_t b[4];
            {
                int k8 = k16 * 2 + b_k8s;
                ldsm4(b[0], b[1], b[2], b[3],
                      bB + b_nloc * 1024 + ((k8 ^ (b_nloc & 7)) << 4));
            }
            mma16816(d[0], a, &b[0]);
            mma16816(d[1], a, &b[2]);
        }

        // stage dot products to smem (pitch 33)
        {
            int r = lane >> 2, cb = 2 * (lane & 3);
            #pragma unroll
            for (int nt = 0; nt < 2; nt++) {
                int col = c0w + nt * 8 + cb;
                scoreS[(row0w + r) * 33 + col]     = d[nt][0];
                scoreS[(row0w + r) * 33 + col + 1] = d[nt][1];
                scoreS[(row0w + r + 8) * 33 + col]     = d[nt][2];
                scoreS[(row0w + r + 8) * 33 + col + 1] = d[nt][3];
            }
        }
        __syncthreads();

        // all 128 threads: local top-8 update over this chunk's 8 cents
        #pragma unroll
        for (int j = 0; j < 8; j++) {
            int   cc  = selpart * 8 + j;
            int   gc  = nc * CCH + cc;
            float val = cnS[gc] - 2.0f * scoreS[selrow * 33 + cc];
            if (ltp(val, gc, tv[NCAND - 1], ti[NCAND - 1])) {
                tv[NCAND - 1] = val; ti[NCAND - 1] = gc;
                #pragma unroll
                for (int q = NCAND - 1; q >= 1; q--)
                    if (ltp(tv[q], ti[q], tv[q - 1], ti[q - 1])) {
                        float fv = tv[q]; tv[q] = tv[q - 1]; tv[q - 1] = fv;
                        int   fi = ti[q]; ti[q] = ti[q - 1]; ti[q - 1] = fi;
                    }
            }
        }
        __syncthreads();
    }

    // ---- merge 4 partial top-8s per row (subsets disjoint => exact) ----
    float* mvS = (float*)(smem + OFF_B0);            // aliases dead B0
    int*   miS = (int*)(smem + OFF_B0 + 4096);
    #pragma unroll
    for (int q = 0; q < NCAND; q++) {
        mvS[(selrow * 4 + selpart) * 8 + q] = tv[q];
        miS[(selrow * 4 + selpart) * 8 + q] = ti[q];
    }
    __syncthreads();
    if (tid < BM) {
        float rv[NCAND]; int ri[NCAND];
        #pragma unroll
        for (int q = 0; q < NCAND; q++) { rv[q] = 3.4e38f; ri[q] = 0x7fffffff; }
        for (int e = 0; e < 32; e++) {
            float v = mvS[tid * 32 + e]; int ix = miS[tid * 32 + e];
            if (ltp(v, ix, rv[NCAND - 1], ri[NCAND - 1])) {
                rv[NCAND - 1] = v; ri[NCAND - 1] = ix;
                #pragma unroll
                for (int q = NCAND - 1; q >= 1; q--)
                    if (ltp(rv[q], ri[q], rv[q - 1], ri[q - 1])) {
                        float fv = rv[q]; rv[q] = rv[q - 1]; rv[q - 1] = fv;
                        int   fi = ri[q]; ri[q] = ri[q - 1]; ri[q - 1] = fi;
                    }
            }
        }
        #pragma unroll
        for (int q = 0; q < NCAND; q++) candS[tid * NCAND + q] = ri[q];
        if (rv[NCAND - 1] - rv[1] <= TAU) {           // containment margin (tight)
            int p = atomicAdd(&g_flag_cnt, 1);
            g_flag_rows[p] = row0 + tid;
        }
    }
    __syncthreads();

    // ---- exact fp32 rescore of 8 candidates: warp w owns rows 8w..8w+8 ----
    for (int i = 0; i < 8; i++) {
        const int row = wid * 8 + i;
        const float4* e4 = (const float4*)(E + (size_t)(row0 + row) * DIM);
        float4 ef[4];
        #pragma unroll
        for (int q = 0; q < 4; q++) ef[q] = e4[lane + 32 * q];
        int cd[NCAND];
        #pragma unroll
        for (int c = 0; c < NCAND; c++) cd[c] = candS[row * NCAND + c];
        float acc[NCAND];
        #pragma unroll
        for (int c = 0; c < NCAND; c++) {
            const float4* c4 = (const float4*)(C + (size_t)cd[c] * DIM);
            float p = 0.0f;
            #pragma unroll
            for (int q = 0; q < 4; q++) {
                float4 cv = c4[lane + 32 * q];
                p = fmaf(ef[q].x, cv.x, p); p = fmaf(ef[q].y, cv.y, p);
                p = fmaf(ef[q].z, cv.z, p); p = fmaf(ef[q].w, cv.w, p);
            }
            acc[c] = p;
        }
        #pragma unroll
        for (int off = 16; off; off >>= 1)
            #pragma unroll
            for (int c = 0; c < NCAND; c++)
                acc[c] += __shfl_xor_sync(0xffffffffu, acc[c], off);
        if (lane == 0) {
            float b1 = 3.4e38f, b2v = 3.4e38f;
            int   i1 = 0x7fffffff, i2 = 0x7fffffff;
            #pragma unroll
            for (int c = 0; c < NCAND; c++) {
                float s = cnS[cd[c]] - 2.0f * acc[c];
                if (ltp(s, cd[c], b1, i1))       { b2v = b1; i2 = i1; b1 = s; i1 = cd[c]; }
                else if (ltp(s, cd[c], b2v, i2)) { b2v = s; i2 = cd[c]; }
            }
            g_idx[row0 + row] = i2;
        }
    }
}

// ---------------------------------------------------------------------------
// Cleanup: warp-per-row exact full rescan (lane-parallel dots, 4-cent ILP).
// ---------------------------------------------------------------------------
__global__ __launch_bounds__(256) void cleanup_kernel(const float* __restrict__ E,
                                                      const float* __restrict__ C)
{
    const int lane = threadIdx.x & 31;
    const int gw   = (blockIdx.x * blockDim.x + threadIdx.x) >> 5;   // global warp id
    const int nflag = g_flag_cnt;
    for (int i = gw; i < nflag; i += 2048) {
        const int row = g_flag_rows[i];
        const float4* e4 = (const float4*)(E + (size_t)row * DIM);
        float4 ef[4];
        #pragma unroll
        for (int q = 0; q < 4; q++) ef[q] = e4[lane + 32 * q];
        float v1 = 3.4e38f, v2 = 3.4e38f;
        int   i1 = 0x7fffffff, i2 = 0x7fffffff;
        for (int k0 = 0; k0 < KC; k0 += 4) {
            float acc[4];
            #pragma unroll
            for (int c = 0; c < 4; c++) {
                const float4* c4 = (const float4*)(C + (size_t)(k0 + c) * DIM);
                float p = 0.0f;
                #pragma unroll
                for (int q = 0; q < 4; q++) {
                    float4 cv = c4[lane + 32 * q];
                    p = fmaf(ef[q].x, cv.x, p); p = fmaf(ef[q].y, cv.y, p);
                    p = fmaf(ef[q].z, cv.z, p); p = fmaf(ef[q].w, cv.w, p);
                }
                acc[c] = p;
            }
            #pragma unroll
            for (int off = 16; off; off >>= 1)
                #pragma unroll
                for (int c = 0; c < 4; c++)
                    acc[c] += __shfl_xor_sync(0xffffffffu, acc[c], off);
            #pragma unroll
            for (int c = 0; c < 4; c++) {
                int k = k0 + c;
                float s = g_cnorm[k] - 2.0f * acc[c];
                if (ltp(s, k, v1, i1))      { v2 = v1; i2 = i1; v1 = s; i1 = k; }
                else if (ltp(s, k, v2, i2)) { v2 = s; i2 = k; }
            }
        }
        if (lane == 0) g_idx[row] = i2;
    }
}

// ---------------------------------------------------------------------------
// Gather: out[row] = C[g_idx[row]]  (measured 22us)
// ---------------------------------------------------------------------------
__global__ __launch_bounds__(256) void gather_kernel(const float* __restrict__ C,
                                                     float* __restrict__ out)
{
    __shared__ int idxS[32];
    const int t = threadIdx.x;
    const int row0 = blockIdx.x * 32;
    if (t < 32) idxS[t] = g_idx[row0 + t];
    __syncthreads();
    #pragma unroll
    for (int j = 0; j < 16; j++) {
        int u = t + 256 * j;                 // 4096 float4 units
        int r = u >> 7, q = u & 127;
        *(float4*)(out + (size_t)(row0 + r) * DIM + q * 4) =
            *(const float4*)(C + (size_t)idxS[r] * DIM + q * 4);
    }
}

extern "C" void kernel_launch(void* const* d_in, const int* in_sizes, int n_in,
                              void* d_out, int out_size) {
    const float* E = (const float*)d_in[0];
    const float* C = (const float*)d_in[1];
    float* out = (float*)d_out;
    (void)in_sizes; (void)n_in; (void)out_size;

    cudaFuncSetAttribute(score_kernel, cudaFuncAttributeMaxDynamicSharedMemorySize, SMEM_TOTAL);
    prep_kernel<<<KC, 128>>>(C);
    score_kernel<<<N_ROWS / BM, NTHR, SMEM_TOTAL>>>(E, C);
    cleanup_kernel<<<256, 256>>>(E, C);
    gather_kernel<<<N_ROWS / 32, 256>>>(C, out);
}

// round 14
// speedup vs baseline: 1.3814x; 1.1697x over previous
#include <cuda_runtime.h>
#include <cuda_bf16.h>
#include <cstdint>

#define N_ROWS 65536
#define DIM    512
#define KC     256
#define BM     32        // rows per CTA
#define CCH    32        // centroids per chunk
#define NCHK   8
#define NTHR   128
#define NCAND  4
#define TAU    1.0f

// smem byte offsets (dynamic)
#define OFF_A    0                 // 32 x 512 bf16 = 32768
#define OFF_B0   32768
#define OFF_B1   65536
#define OFF_CN   98304             // 256 f32 = 1024
#define OFF_MV   99328             // 32 rows x 2 halves x 4 floats = 1024
#define OFF_MI   100352            // same, ints = 1024
#define OFF_CAND 101376            // 32 x 4 int = 512
#define SMEM_TOTAL 101888          // <114KB -> 2 CTAs/SM

__device__ __nv_bfloat16 g_Bbf[KC][DIM];
__device__ float g_cnorm[KC];
__device__ int   g_idx[N_ROWS];
__device__ int   g_flag_cnt;
__device__ int   g_flag_rows[N_ROWS];

__device__ __forceinline__ uint32_t smem_u32(const void* p) {
    uint32_t a;
    asm("{ .reg .u64 t; cvta.to.shared.u64 t, %1; cvt.u32.u64 %0, t; }" : "=r"(a) : "l"(p));
    return a;
}
__device__ __forceinline__ void cp16(uint32_t s, const void* g) {
    asm volatile("cp.async.cg.shared.global [%0], [%1], 16;" :: "r"(s), "l"(g) : "memory");
}
__device__ __forceinline__ void ldsm4(uint32_t& r0, uint32_t& r1, uint32_t& r2, uint32_t& r3, uint32_t a) {
    asm volatile("ldmatrix.sync.aligned.m8n8.x4.shared.b16 {%0,%1,%2,%3}, [%4];"
                 : "=r"(r0), "=r"(r1), "=r"(r2), "=r"(r3) : "r"(a));
}
__device__ __forceinline__ void mma16816(float* d, const uint32_t* a, const uint32_t* b) {
    asm volatile("mma.sync.aligned.m16n8k16.row.col.f32.bf16.bf16.f32 "
                 "{%0,%1,%2,%3}, {%4,%5,%6,%7}, {%8,%9}, {%0,%1,%2,%3};"
                 : "+f"(d[0]), "+f"(d[1]), "+f"(d[2]), "+f"(d[3])
                 : "r"(a[0]), "r"(a[1]), "r"(a[2]), "r"(a[3]), "r"(b[0]), "r"(b[1]));
}
__device__ __forceinline__ uint32_t b2u(__nv_bfloat162 v) {
    return ((uint32_t)__bfloat16_as_ushort(v.y) << 16) | __bfloat16_as_ushort(v.x);
}
__device__ __forceinline__ bool ltp(float a, int ia, float b, int ib) {
    return a < b || (a == b && ia < ib);
}
// insert (v,ix) into descending-priority sorted top-4 (best at [0])
__device__ __forceinline__ void ins4(float* tv, int* ti, float v, int ix) {
    if (ltp(v, ix, tv[3], ti[3])) {
        tv[3] = v; ti[3] = ix;
        #pragma unroll
        for (int q = 3; q >= 1; q--)
            if (ltp(tv[q], ti[q], tv[q - 1], ti[q - 1])) {
                float fv = tv[q]; tv[q] = tv[q - 1]; tv[q - 1] = fv;
                int   fi = ti[q]; ti[q] = ti[q - 1]; ti[q - 1] = fi;
            }
    }
}

// ---------------------------------------------------------------------------
__global__ void prep_kernel(const float* __restrict__ C) {
    __shared__ double red[4];
    const int k = blockIdx.x, t = threadIdx.x;   // 128 thr
    if (k == 0 && t == 0) g_flag_cnt = 0;
    double s = 0.0;
    for (int d = t; d < DIM; d += 128) {
        float v = C[(size_t)k * DIM + d];
        s += (double)v * (double)v;
        g_Bbf[k][d] = __float2bfloat16_rn(v);
    }
    #pragma unroll
    for (int o = 16; o; o >>= 1) s += __shfl_xor_sync(0xffffffffu, s, o);
    if ((t & 31) == 0) red[t >> 5] = s;
    __syncthreads();
    if (t == 0) g_cnorm[k] = (float)(red[0] + red[1] + red[2] + red[3]);
}

// ---------------------------------------------------------------------------
// Score: 32 rows x 256 cents per CTA. HMMA coarse; selection lives entirely
// in registers (per-thread disjoint column subsets), merged by shfl + one
// tiny smem pass. Exact fp32 rescore of 4 candidates; margin-flag the rest.
// ---------------------------------------------------------------------------
__global__ __launch_bounds__(NTHR, 2) void score_kernel(
    const float* __restrict__ E, const float* __restrict__ C)
{
    extern __shared__ __align__(1024) char smem[];
    const uint32_t sb = smem_u32(smem);
    const int tid  = threadIdx.x;
    const int wid  = tid >> 5;      // 0..3
    const int lane = tid & 31;
    const int row0 = blockIdx.x * BM;

    float* cnS   = (float*)(smem + OFF_CN);
    float* mvS   = (float*)(smem + OFF_MV);
    int*   miS   = (int*)(smem + OFF_MI);
    int*   candS = (int*)(smem + OFF_CAND);

    for (int i = tid; i < KC; i += NTHR) cnS[i] = g_cnorm[i];

    // ---- prefetch B chunk 0 ----
    {
        const char* bsrc = (const char*)g_Bbf;
        #pragma unroll
        for (int j = 0; j < 16; j++) {
            int u = tid + NTHR * j;              // 2048 16B units
            int n = u >> 6, c = u & 63;
            cp16(sb + OFF_B0 + n * 1024 + ((c ^ (n & 7)) << 4), bsrc + n * 1024 + c * 16);
        }
        asm volatile("cp.async.commit_group;" ::: "memory");
    }

    // ---- fill A: 32 rows of E, f32 -> bf16, swizzled ----
    #pragma unroll
    for (int j = 0; j < 32; j++) {
        int u = tid + NTHR * j;                  // 4096 float4 units
        int r = u >> 7, q = u & 127;
        float4 f = *(const float4*)(E + (size_t)(row0 + r) * DIM + q * 4);
        uint2 v = make_uint2(b2u(__floats2bfloat162_rn(f.x, f.y)),
                             b2u(__floats2bfloat162_rn(f.z, f.w)));
        uint32_t off = r * 1024 + (((q >> 1) ^ (r & 7)) << 4) + ((q & 1) << 3);
        *(uint2*)(smem + OFF_A + off) = v;
    }

    const int row0w = (wid & 1) * 16;     // row group of this warp
    const int c0w   = (wid >> 1) * 16;    // col half of this warp (within chunk)
    const int a_row  = row0w + (lane & 7) + ((lane >> 3) & 1) * 8;
    const int a_k8s  = (lane >> 4);
    const int b_nloc = c0w + ((lane >> 4) & 1) * 8 + (lane & 7);
    const int b_k8s  = (lane >> 3) & 1;

    // fragment cell geometry for selection
    const int frow = lane >> 2;           // within row group: rows frow, frow+8
    const int fcb  = 2 * (lane & 3);      // col pair base within 8-col tile

    // per-thread top-4 for its two rows (disjoint column subsets)
    float vA[4], vB[4]; int iA[4], iB[4];
    #pragma unroll
    for (int q = 0; q < 4; q++) {
        vA[q] = vB[q] = 3.4e38f; iA[q] = iB[q] = 0x7fffffff;
    }

    for (int nc = 0; nc < NCHK; nc++) {
        if (nc + 1 < NCHK) {
            const char* bsrc = (const char*)g_Bbf + (size_t)(nc + 1) * CCH * 1024;
            uint32_t bdst = sb + (((nc + 1) & 1) ? OFF_B1 : OFF_B0);
            #pragma unroll
            for (int j = 0; j < 16; j++) {
                int u = tid + NTHR * j;
                int n = u >> 6, c = u & 63;
                cp16(bdst + n * 1024 + ((c ^ (n & 7)) << 4), bsrc + n * 1024 + c * 16);
            }
            asm volatile("cp.async.commit_group;" ::: "memory");
            asm volatile("cp.async.wait_group 1;" ::: "memory");
        } else {
            asm volatile("cp.async.wait_group 0;" ::: "memory");
        }
        __syncthreads();

        const uint32_t aB = sb + OFF_A;
        const uint32_t bB = sb + ((nc & 1) ? OFF_B1 : OFF_B0);

        float d[2][4];
        #pragma unroll
        for (int nt = 0; nt < 2; nt++)
            #pragma unroll
            for (int e = 0; e < 4; e++) d[nt][e] = 0.0f;

        #pragma unroll 4
        for (int k16 = 0; k16 < 32; k16++) {
            uint32_t a[4];
            {
                int k8 = k16 * 2 + a_k8s;
                ldsm4(a[0], a[1], a[2], a[3],
                      aB + a_row * 1024 + ((k8 ^ (a_row & 7)) << 4));
            }
            uint32_t b[4];
            {
                int k8 = k16 * 2 + b_k8s;
                ldsm4(b[0], b[1], b[2], b[3],
                      bB + b_nloc * 1024 + ((k8 ^ (b_nloc & 7)) << 4));
            }
            mma16816(d[0], a, &b[0]);
            mma16816(d[1], a, &b[2]);
        }

        // ---- selection directly from accumulators (no smem, no barrier) ----
        #pragma unroll
        for (int nt = 0; nt < 2; nt++) {
            int gc = nc * CCH + c0w + nt * 8 + fcb;     // global centroid col
            float s0 = cnS[gc]     - 2.0f * d[nt][0];   // row frow
            float s1 = cnS[gc + 1] - 2.0f * d[nt][1];
            float s2 = cnS[gc]     - 2.0f * d[nt][2];   // row frow+8
            float s3 = cnS[gc + 1] - 2.0f * d[nt][3];
            ins4(vA, iA, s0, gc); ins4(vA, iA, s1, gc + 1);
            ins4(vB, iB, s2, gc); ins4(vB, iB, s3, gc + 1);
        }
        __syncthreads();   // protect B buffer reuse
    }

    // ---- merge across the 4 lanes sharing each row (disjoint cols => exact) ----
    #pragma unroll
    for (int st = 1; st <= 2; st <<= 1) {
        float ov[4]; int oi[4];
        #pragma unroll
        for (int q = 0; q < 4; q++) {
            ov[q] = __shfl_xor_sync(0xffffffffu, vA[q], st);
            oi[q] = __shfl_xor_sync(0xffffffffu, iA[q], st);
        }
        #pragma unroll
        for (int q = 0; q < 4; q++) ins4(vA, iA, ov[q], oi[q]);
        #pragma unroll
        for (int q = 0; q < 4; q++) {
            ov[q] = __shfl_xor_sync(0xffffffffu, vB[q], st);
            oi[q] = __shfl_xor_sync(0xffffffffu, iB[q], st);
        }
        #pragma unroll
        for (int q = 0; q < 4; q++) ins4(vB, iB, ov[q], oi[q]);
    }
    // publish per-warp row top-4 (half = col half)
    if ((lane & 3) == 0) {
        int half = wid >> 1;
        int rA = row0w + frow, rB = rA + 8;
        #pragma unroll
        for (int q = 0; q < 4; q++) {
            mvS[(rA * 2 + half) * 4 + q] = vA[q];
            miS[(rA * 2 + half) * 4 + q] = iA[q];
            mvS[(rB * 2 + half) * 4 + q] = vB[q];
            miS[(rB * 2 + half) * 4 + q] = iB[q];
        }
    }
    __syncthreads();

    // ---- final per-row merge of 2 halves + margin flag (threads 0..31) ----
    if (tid < BM) {
        float rv[4]; int ri[4];
        #pragma unroll
        for (int q = 0; q < 4; q++) {
            rv[q] = mvS[(tid * 2) * 4 + q];
            ri[q] = miS[(tid * 2) * 4 + q];
        }
        #pragma unroll
        for (int q = 0; q < 4; q++)
            ins4(rv, ri, mvS[(tid * 2 + 1) * 4 + q], miS[(tid * 2 + 1) * 4 + q]);
        #pragma unroll
        for (int q = 0; q < NCAND; q++) candS[tid * NCAND + q] = ri[q];
        if (rv[3] - rv[1] <= TAU) {
            int p = atomicAdd(&g_flag_cnt, 1);
            g_flag_rows[p] = row0 + tid;
        }
    }
    __syncthreads();

    // ---- exact fp32 rescore of 4 candidates: warp w owns rows 8w..8w+8 ----
    for (int i = 0; i < 8; i++) {
        const int row = wid * 8 + i;
        const float4* e4 = (const float4*)(E + (size_t)(row0 + row) * DIM);
        float4 ef[4];
        #pragma unroll
        for (int q = 0; q < 4; q++) ef[q] = e4[lane + 32 * q];
        int cd[NCAND];
        #pragma unroll
        for (int c = 0; c < NCAND; c++) cd[c] = candS[row * NCAND + c];
        float acc[NCAND];
        #pragma unroll
        for (int c = 0; c < NCAND; c++) {
            const float4* c4 = (const float4*)(C + (size_t)cd[c] * DIM);
            float p = 0.0f;
            #pragma unroll
            for (int q = 0; q < 4; q++) {
                float4 cv = c4[lane + 32 * q];
                p = fmaf(ef[q].x, cv.x, p); p = fmaf(ef[q].y, cv.y, p);
                p = fmaf(ef[q].z, cv.z, p); p = fmaf(ef[q].w, cv.w, p);
            }
            acc[c] = p;
        }
        #pragma unroll
        for (int off = 16; off; off >>= 1)
            #pragma unroll
            for (int c = 0; c < NCAND; c++)
                acc[c] += __shfl_xor_sync(0xffffffffu, acc[c], off);
        if (lane == 0) {
            float b1 = 3.4e38f, b2v = 3.4e38f;
            int   i1 = 0x7fffffff, i2 = 0x7fffffff;
            #pragma unroll
            for (int c = 0; c < NCAND; c++) {
                float s = cnS[cd[c]] - 2.0f * acc[c];
                if (ltp(s, cd[c], b1, i1))       { b2v = b1; i2 = i1; b1 = s; i1 = cd[c]; }
                else if (ltp(s, cd[c], b2v, i2)) { b2v = s; i2 = cd[c]; }
            }
            g_idx[row0 + row] = i2;
        }
    }
}

// ---------------------------------------------------------------------------
// Cleanup: warp-per-row exact full rescan (lane-parallel dots, 4-cent ILP).
// ---------------------------------------------------------------------------
__global__ __launch_bounds__(256) void cleanup_kernel(const float* __restrict__ E,
                                                      const float* __restrict__ C)
{
    const int lane = threadIdx.x & 31;
    const int gw   = (blockIdx.x * blockDim.x + threadIdx.x) >> 5;
    const int nflag = g_flag_cnt;
    for (int i = gw; i < nflag; i += 2048) {
        const int row = g_flag_rows[i];
        const float4* e4 = (const float4*)(E + (size_t)row * DIM);
        float4 ef[4];
        #pragma unroll
        for (int q = 0; q < 4; q++) ef[q] = e4[lane + 32 * q];
        float v1 = 3.4e38f, v2 = 3.4e38f;
        int   i1 = 0x7fffffff, i2 = 0x7fffffff;
        for (int k0 = 0; k0 < KC; k0 += 4) {
            float acc[4];
            #pragma unroll
            for (int c = 0; c < 4; c++) {
                const float4* c4 = (const float4*)(C + (size_t)(k0 + c) * DIM);
                float p = 0.0f;
                #pragma unroll
                for (int q = 0; q < 4; q++) {
                    float4 cv = c4[lane + 32 * q];
                    p = fmaf(ef[q].x, cv.x, p); p = fmaf(ef[q].y, cv.y, p);
                    p = fmaf(ef[q].z, cv.z, p); p = fmaf(ef[q].w, cv.w, p);
                }
                acc[c] = p;
            }
            #pragma unroll
            for (int off = 16; off; off >>= 1)
                #pragma unroll
                for (int c = 0; c < 4; c++)
                    acc[c] += __shfl_xor_sync(0xffffffffu, acc[c], off);
            #pragma unroll
            for (int c = 0; c < 4; c++) {
                int k = k0 + c;
                float s = g_cnorm[k] - 2.0f * acc[c];
                if (ltp(s, k, v1, i1))      { v2 = v1; i2 = i1; v1 = s; i1 = k; }
                else if (ltp(s, k, v2, i2)) { v2 = s; i2 = k; }
            }
        }
        if (lane == 0) g_idx[row] = i2;
    }
}

// ---------------------------------------------------------------------------
// Gather: out[row] = C[g_idx[row]]
// ---------------------------------------------------------------------------
__global__ __launch_bounds__(256) void gather_kernel(const float* __restrict__ C,
                                                     float* __restrict__ out)
{
    __shared__ int idxS[32];
    const int t = threadIdx.x;
    const int row0 = blockIdx.x * 32;
    if (t < 32) idxS[t] = g_idx[row0 + t];
    __syncthreads();
    #pragma unroll
    for (int j = 0; j < 16; j++) {
        int u = t + 256 * j;
        int r = u >> 7, q = u & 127;
        *(float4*)(out + (size_t)(row0 + r) * DIM + q * 4) =
            *(const float4*)(C + (size_t)idxS[r] * DIM + q * 4);
    }
}

extern "C" void kernel_launch(void* const* d_in, const int* in_sizes, int n_in,
                              void* d_out, int out_size) {
    const float* E = (const float*)d_in[0];
    const float* C = (const float*)d_in[1];
    float* out = (float*)d_out;
    (void)in_sizes; (void)n_in; (void)out_size;

    cudaFuncSetAttribute(score_kernel, cudaFuncAttributeMaxDynamicSharedMemorySize, SMEM_TOTAL);
    prep_kernel<<<KC, 128>>>(C);
    score_kernel<<<N_ROWS / BM, NTHR, SMEM_TOTAL>>>(E, C);
    cleanup_kernel<<<256, 256>>>(E, C);
    gather_kernel<<<N_ROWS / 32, 256>>>(C, out);
}

// round 15
// speedup vs baseline: 1.4313x; 1.0362x over previous
#include <cuda_runtime.h>
#include <cuda_bf16.h>
#include <cstdint>

#define N_ROWS 65536
#define DIM    512
#define KC     256
#define BM     32        // rows per CTA
#define CCH    32        // centroids per chunk
#define NCHK   8
#define NTHR   256
#define NCAND  4
#define TAU    1.0f

// smem byte offsets (dynamic)
#define OFF_A    0                 // 32 x 512 bf16 = 32768
#define OFF_B0   32768
#define OFF_B1   65536
#define OFF_CN   98304             // 256 f32 = 1024
#define OFF_MV   99328             // 32 rows x 4 groups x 4 floats = 2048
#define OFF_MI   101376            // same, ints = 2048
#define OFF_CAND 103424            // 32 x 4 int = 512
#define SMEM_TOTAL 103936          // ~101.5KB -> 2 CTAs/SM (16 warps/SM)

__device__ __nv_bfloat16 g_Bbf[KC][DIM];
__device__ float g_cnorm[KC];
__device__ int   g_idx[N_ROWS];
__device__ int   g_flag_cnt;
__device__ int   g_flag_rows[N_ROWS];

__device__ __forceinline__ uint32_t smem_u32(const void* p) {
    uint32_t a;
    asm("{ .reg .u64 t; cvta.to.shared.u64 t, %1; cvt.u32.u64 %0, t; }" : "=r"(a) : "l"(p));
    return a;
}
__device__ __forceinline__ void cp16(uint32_t s, const void* g) {
    asm volatile("cp.async.cg.shared.global [%0], [%1], 16;" :: "r"(s), "l"(g) : "memory");
}
__device__ __forceinline__ void ldsm4(uint32_t& r0, uint32_t& r1, uint32_t& r2, uint32_t& r3, uint32_t a) {
    asm volatile("ldmatrix.sync.aligned.m8n8.x4.shared.b16 {%0,%1,%2,%3}, [%4];"
                 : "=r"(r0), "=r"(r1), "=r"(r2), "=r"(r3) : "r"(a));
}
__device__ __forceinline__ void ldsm2(uint32_t& r0, uint32_t& r1, uint32_t a) {
    asm volatile("ldmatrix.sync.aligned.m8n8.x2.shared.b16 {%0,%1}, [%2];"
                 : "=r"(r0), "=r"(r1) : "r"(a));
}
__device__ __forceinline__ void mma16816(float* d, const uint32_t* a, const uint32_t* b) {
    asm volatile("mma.sync.aligned.m16n8k16.row.col.f32.bf16.bf16.f32 "
                 "{%0,%1,%2,%3}, {%4,%5,%6,%7}, {%8,%9}, {%0,%1,%2,%3};"
                 : "+f"(d[0]), "+f"(d[1]), "+f"(d[2]), "+f"(d[3])
                 : "r"(a[0]), "r"(a[1]), "r"(a[2]), "r"(a[3]), "r"(b[0]), "r"(b[1]));
}
__device__ __forceinline__ uint32_t b2u(__nv_bfloat162 v) {
    return ((uint32_t)__bfloat16_as_ushort(v.y) << 16) | __bfloat16_as_ushort(v.x);
}
__device__ __forceinline__ bool ltp(float a, int ia, float b, int ib) {
    return a < b || (a == b && ia < ib);
}
__device__ __forceinline__ void ins4(float* tv, int* ti, float v, int ix) {
    if (ltp(v, ix, tv[3], ti[3])) {
        tv[3] = v; ti[3] = ix;
        #pragma unroll
        for (int q = 3; q >= 1; q--)
            if (ltp(tv[q], ti[q], tv[q - 1], ti[q - 1])) {
                float fv = tv[q]; tv[q] = tv[q - 1]; tv[q - 1] = fv;
                int   fi = ti[q]; ti[q] = ti[q - 1]; ti[q - 1] = fi;
            }
    }
}

// ---------------------------------------------------------------------------
__global__ void prep_kernel(const float* __restrict__ C) {
    __shared__ double red[4];
    const int k = blockIdx.x, t = threadIdx.x;   // 128 thr
    if (k == 0 && t == 0) g_flag_cnt = 0;
    double s = 0.0;
    for (int d = t; d < DIM; d += 128) {
        float v = C[(size_t)k * DIM + d];
        s += (double)v * (double)v;
        g_Bbf[k][d] = __float2bfloat16_rn(v);
    }
    #pragma unroll
    for (int o = 16; o; o >>= 1) s += __shfl_xor_sync(0xffffffffu, s, o);
    if ((t & 31) == 0) red[t >> 5] = s;
    __syncthreads();
    if (t == 0) g_cnorm[k] = (float)(red[0] + red[1] + red[2] + red[3]);
}

// ---------------------------------------------------------------------------
// Score: 32 rows x 256 cents per CTA, 8 warps (warp = 16 rows x 8 cols).
// HMMA coarse; register-resident top-4 selection; exact fp32 rescore of 4
// candidates; margin-flag -> cleanup.
// ---------------------------------------------------------------------------
__global__ __launch_bounds__(NTHR, 2) void score_kernel(
    const float* __restrict__ E, const float* __restrict__ C)
{
    extern __shared__ __align__(1024) char smem[];
    const uint32_t sb = smem_u32(smem);
    const int tid  = threadIdx.x;
    const int wid  = tid >> 5;      // 0..7
    const int lane = tid & 31;
    const int row0 = blockIdx.x * BM;

    float* cnS   = (float*)(smem + OFF_CN);
    float* mvS   = (float*)(smem + OFF_MV);
    int*   miS   = (int*)(smem + OFF_MI);
    int*   candS = (int*)(smem + OFF_CAND);

    for (int i = tid; i < KC; i += NTHR) cnS[i] = g_cnorm[i];

    // ---- prefetch B chunk 0 ----
    {
        const char* bsrc = (const char*)g_Bbf;
        #pragma unroll
        for (int j = 0; j < 8; j++) {
            int u = tid + NTHR * j;              // 2048 16B units
            int n = u >> 6, c = u & 63;
            cp16(sb + OFF_B0 + n * 1024 + ((c ^ (n & 7)) << 4), bsrc + n * 1024 + c * 16);
        }
        asm volatile("cp.async.commit_group;" ::: "memory");
    }

    // ---- fill A: 32 rows of E, f32 -> bf16, swizzled ----
    #pragma unroll
    for (int j = 0; j < 16; j++) {
        int u = tid + NTHR * j;                  // 4096 float4 units
        int r = u >> 7, q = u & 127;
        float4 f = *(const float4*)(E + (size_t)(row0 + r) * DIM + q * 4);
        uint2 v = make_uint2(b2u(__floats2bfloat162_rn(f.x, f.y)),
                             b2u(__floats2bfloat162_rn(f.z, f.w)));
        uint32_t off = r * 1024 + (((q >> 1) ^ (r & 7)) << 4) + ((q & 1) << 3);
        *(uint2*)(smem + OFF_A + off) = v;
    }

    const int rowg = wid & 1;             // row group: rows rowg*16 .. +16
    const int colg = wid >> 1;            // col group: cols colg*8 .. +8 (in chunk)
    const int row0w = rowg * 16;
    const int c0w   = colg * 8;
    const int a_row  = row0w + (lane & 7) + ((lane >> 3) & 1) * 8;
    const int a_k8s  = (lane >> 4);
    const int b_nloc = c0w + (lane & 7);          // lanes 0..15 meaningful
    const int b_k8s  = (lane >> 3) & 1;

    const int frow = lane >> 2;           // fragment row within group
    const int fcb  = 2 * (lane & 3);      // fragment col pair base

    float vA[4], vB[4]; int iA[4], iB[4];
    #pragma unroll
    for (int q = 0; q < 4; q++) {
        vA[q] = vB[q] = 3.4e38f; iA[q] = iB[q] = 0x7fffffff;
    }

    for (int nc = 0; nc < NCHK; nc++) {
        if (nc + 1 < NCHK) {
            const char* bsrc = (const char*)g_Bbf + (size_t)(nc + 1) * CCH * 1024;
            uint32_t bdst = sb + (((nc + 1) & 1) ? OFF_B1 : OFF_B0);
            #pragma unroll
            for (int j = 0; j < 8; j++) {
                int u = tid + NTHR * j;
                int n = u >> 6, c = u & 63;
                cp16(bdst + n * 1024 + ((c ^ (n & 7)) << 4), bsrc + n * 1024 + c * 16);
            }
            asm volatile("cp.async.commit_group;" ::: "memory");
            asm volatile("cp.async.wait_group 1;" ::: "memory");
        } else {
            asm volatile("cp.async.wait_group 0;" ::: "memory");
        }
        __syncthreads();

        const uint32_t aB = sb + OFF_A;
        const uint32_t bB = sb + ((nc & 1) ? OFF_B1 : OFF_B0);

        float d[4] = {0.0f, 0.0f, 0.0f, 0.0f};

        #pragma unroll 8
        for (int k16 = 0; k16 < 32; k16++) {
            uint32_t a[4];
            {
                int k8 = k16 * 2 + a_k8s;
                ldsm4(a[0], a[1], a[2], a[3],
                      aB + a_row * 1024 + ((k8 ^ (a_row & 7)) << 4));
            }
            uint32_t b[2];
            {
                int k8 = k16 * 2 + b_k8s;
                ldsm2(b[0], b[1],
                      bB + b_nloc * 1024 + ((k8 ^ (b_nloc & 7)) << 4));
            }
            mma16816(d, a, b);
        }

        // ---- selection directly from accumulators ----
        {
            int gc = nc * CCH + c0w + fcb;
            float s0 = cnS[gc]     - 2.0f * d[0];
            float s1 = cnS[gc + 1] - 2.0f * d[1];
            float s2 = cnS[gc]     - 2.0f * d[2];
            float s3 = cnS[gc + 1] - 2.0f * d[3];
            ins4(vA, iA, s0, gc); ins4(vA, iA, s1, gc + 1);
            ins4(vB, iB, s2, gc); ins4(vB, iB, s3, gc + 1);
        }
        __syncthreads();   // protect B buffer reuse
    }

    // ---- merge across the 4 lanes sharing each row (disjoint cols) ----
    #pragma unroll
    for (int st = 1; st <= 2; st <<= 1) {
        float ov[4]; int oi[4];
        #pragma unroll
        for (int q = 0; q < 4; q++) {
            ov[q] = __shfl_xor_sync(0xffffffffu, vA[q], st);
            oi[q] = __shfl_xor_sync(0xffffffffu, iA[q], st);
        }
        #pragma unroll
        for (int q = 0; q < 4; q++) ins4(vA, iA, ov[q], oi[q]);
        #pragma unroll
        for (int q = 0; q < 4; q++) {
            ov[q] = __shfl_xor_sync(0xffffffffu, vB[q], st);
            oi[q] = __shfl_xor_sync(0xffffffffu, iB[q], st);
        }
        #pragma unroll
        for (int q = 0; q < 4; q++) ins4(vB, iB, ov[q], oi[q]);
    }
    // publish per-warp row top-4 into [row][colg] slots
    if ((lane & 3) == 0) {
        int rA = row0w + frow, rB = rA + 8;
        #pragma unroll
        for (int q = 0; q < 4; q++) {
            mvS[(rA * 4 + colg) * 4 + q] = vA[q];
            miS[(rA * 4 + colg) * 4 + q] = iA[q];
            mvS[(rB * 4 + colg) * 4 + q] = vB[q];
            miS[(rB * 4 + colg) * 4 + q] = iB[q];
        }
    }
    __syncthreads();

    // ---- final per-row merge of 4 col groups + margin flag (threads 0..31) ----
    if (tid < BM) {
        float rv[4]; int ri[4];
        #pragma unroll
        for (int q = 0; q < 4; q++) {
            rv[q] = mvS[(tid * 4) * 4 + q];
            ri[q] = miS[(tid * 4) * 4 + q];
        }
        #pragma unroll
        for (int g = 1; g < 4; g++)
            #pragma unroll
            for (int q = 0; q < 4; q++)
                ins4(rv, ri, mvS[(tid * 4 + g) * 4 + q], miS[(tid * 4 + g) * 4 + q]);
        #pragma unroll
        for (int q = 0; q < NCAND; q++) candS[tid * NCAND + q] = ri[q];
        if (rv[3] - rv[1] <= TAU) {
            int p = atomicAdd(&g_flag_cnt, 1);
            g_flag_rows[p] = row0 + tid;
        }
    }
    __syncthreads();

    // ---- exact fp32 rescore of 4 candidates: warp w owns rows 4w..4w+4 ----
    for (int i = 0; i < 4; i++) {
        const int row = wid * 4 + i;
        const float4* e4 = (const float4*)(E + (size_t)(row0 + row) * DIM);
        float4 ef[4];
        #pragma unroll
        for (int q = 0; q < 4; q++) ef[q] = e4[lane + 32 * q];
        int cd[NCAND];
        #pragma unroll
        for (int c = 0; c < NCAND; c++) cd[c] = candS[row * NCAND + c];
        float acc[NCAND];
        #pragma unroll
        for (int c = 0; c < NCAND; c++) {
            const float4* c4 = (const float4*)(C + (size_t)cd[c] * DIM);
            float p = 0.0f;
            #pragma unroll
            for (int q = 0; q < 4; q++) {
                float4 cv = c4[lane + 32 * q];
                p = fmaf(ef[q].x, cv.x, p); p = fmaf(ef[q].y, cv.y, p);
                p = fmaf(ef[q].z, cv.z, p); p = fmaf(ef[q].w, cv.w, p);
            }
            acc[c] = p;
        }
        #pragma unroll
        for (int off = 16; off; off >>= 1)
            #pragma unroll
            for (int c = 0; c < NCAND; c++)
                acc[c] += __shfl_xor_sync(0xffffffffu, acc[c], off);
        if (lane == 0) {
            float b1 = 3.4e38f, b2v = 3.4e38f;
            int   i1 = 0x7fffffff, i2 = 0x7fffffff;
            #pragma unroll
            for (int c = 0; c < NCAND; c++) {
                float s = cnS[cd[c]] - 2.0f * acc[c];
                if (ltp(s, cd[c], b1, i1))       { b2v = b1; i2 = i1; b1 = s; i1 = cd[c]; }
                else if (ltp(s, cd[c], b2v, i2)) { b2v = s; i2 = cd[c]; }
            }
            g_idx[row0 + row] = i2;
        }
    }
}

// ---------------------------------------------------------------------------
// Cleanup: warp-per-row exact full rescan.
// ---------------------------------------------------------------------------
__global__ __launch_bounds__(256) void cleanup_kernel(const float* __restrict__ E,
                                                      const float* __restrict__ C)
{
    const int lane = threadIdx.x & 31;
    const int gw   = (blockIdx.x * blockDim.x + threadIdx.x) >> 5;
    const int nflag = g_flag_cnt;
    for (int i = gw; i < nflag; i += 2048) {
        const int row = g_flag_rows[i];
        const float4* e4 = (const float4*)(E + (size_t)row * DIM);
        float4 ef[4];
        #pragma unroll
        for (int q = 0; q < 4; q++) ef[q] = e4[lane + 32 * q];
        float v1 = 3.4e38f, v2 = 3.4e38f;
        int   i1 = 0x7fffffff, i2 = 0x7fffffff;
        for (int k0 = 0; k0 < KC; k0 += 4) {
            float acc[4];
            #pragma unroll
            for (int c = 0; c < 4; c++) {
                const float4* c4 = (const float4*)(C + (size_t)(k0 + c) * DIM);
                float p = 0.0f;
                #pragma unroll
                for (int q = 0; q < 4; q++) {
                    float4 cv = c4[lane + 32 * q];
                    p = fmaf(ef[q].x, cv.x, p); p = fmaf(ef[q].y, cv.y, p);
                    p = fmaf(ef[q].z, cv.z, p); p = fmaf(ef[q].w, cv.w, p);
                }
                acc[c] = p;
            }
            #pragma unroll
            for (int off = 16; off; off >>= 1)
                #pragma unroll
                for (int c = 0; c < 4; c++)
                    acc[c] += __shfl_xor_sync(0xffffffffu, acc[c], off);
            #pragma unroll
            for (int c = 0; c < 4; c++) {
                int k = k0 + c;
                float s = g_cnorm[k] - 2.0f * acc[c];
                if (ltp(s, k, v1, i1))      { v2 = v1; i2 = i1; v1 = s; i1 = k; }
                else if (ltp(s, k, v2, i2)) { v2 = s; i2 = k; }
            }
        }
        if (lane == 0) g_idx[row] = i2;
    }
}

// ---------------------------------------------------------------------------
// Gather: out[row] = C[g_idx[row]]
// ---------------------------------------------------------------------------
__global__ __launch_bounds__(256) void gather_kernel(const float* __restrict__ C,
                                                     float* __restrict__ out)
{
    __shared__ int idxS[32];
    const int t = threadIdx.x;
    const int row0 = blockIdx.x * 32;
    if (t < 32) idxS[t] = g_idx[row0 + t];
    __syncthreads();
    #pragma unroll
    for (int j = 0; j < 16; j++) {
        int u = t + 256 * j;
        int r = u >> 7, q = u & 127;
        *(float4*)(out + (size_t)(row0 + r) * DIM + q * 4) =
            *(const float4*)(C + (size_t)idxS[r] * DIM + q * 4);
    }
}

extern "C" void kernel_launch(void* const* d_in, const int* in_sizes, int n_in,
                              void* d_out, int out_size) {
    const float* E = (const float*)d_in[0];
    const float* C = (const float*)d_in[1];
    float* out = (float*)d_out;
    (void)in_sizes; (void)n_in; (void)out_size;

    cudaFuncSetAttribute(score_kernel, cudaFuncAttributeMaxDynamicSharedMemorySize, SMEM_TOTAL);
    prep_kernel<<<KC, 128>>>(C);
    score_kernel<<<N_ROWS / BM, NTHR, SMEM_TOTAL>>>(E, C);
    cleanup_kernel<<<256, 256>>>(E, C);
    gather_kernel<<<N_ROWS / 32, 256>>>(C, out);
}